// round 9
// baseline (speedup 1.0000x reference)
#include <cuda_runtime.h>
#include <cstdint>

#define BB 16
#define TT 512
#define DD 384
#define OUT_LEN 3584            // T * (MAX_DUR - 1)
#define ROWS 64                 // output rows per block
#define BLOCKS_PER_B (OUT_LEN / ROWS)   // 56
#define NT 256
#define V4 (DD / 4)             // 96 float4 per row
#define ITERS ((ROWS * V4) / NT)        // 24

// Fused: one block scan per 64 output rows (8x amortized vs R8) +
// searchsorted + direct LDG.128 -> STG.128 gather. smem ~2.3 KB.
__global__ void __launch_bounds__(NT, 6)
lr_fused(const float* __restrict__ xs, const int* __restrict__ ds,
         const int* __restrict__ ilens, float* __restrict__ out) {
    __shared__ int csum[TT];
    __shared__ int wtot[8];
    __shared__ int srcs[ROWS];

    const int tid = threadIdx.x;
    const int lane = tid & 31;
    const int w = tid >> 5;               // 8 warps
    const int b = blockIdx.y;
    const int r0 = blockIdx.x * ROWS;

    // ---- masked duration load: 2 consecutive per thread ----
    const int ilen = __ldg(ilens + b);
    int2 dv = ((const int2*)(ds + b * TT))[tid];
    const int g0 = tid * 2;
    int d0 = (g0 + 0 < ilen) ? dv.x : 0;
    int d1 = (g0 + 1 < ilen) ? dv.y : 0;
    int p1 = d0 + d1;

    // ---- block inclusive scan -> csum ----
    int x = p1;
    #pragma unroll
    for (int off = 1; off < 32; off <<= 1) {
        int y = __shfl_up_sync(0xFFFFFFFFu, x, off);
        if (lane >= off) x += y;
    }
    if (lane == 31) wtot[w] = x;
    __syncthreads();
    int woff = 0;
    #pragma unroll
    for (int i = 0; i < 8; ++i) woff += (i < w) ? wtot[i] : 0;
    const int excl = woff + x - p1;
    csum[g0 + 0] = excl + d0;
    csum[g0 + 1] = excl + p1;
    __syncthreads();

    const int total = csum[TT - 1];
    const int p = min(max(total - r0, 0), ROWS);   // valid rows are a prefix

    // ---- searchsorted(csum, t, 'right'): 10 halvings for [0,512] ----
    if (tid < ROWS) {
        int s = -1;
        if (tid < p) {
            const int t = r0 + tid;
            int lo = 0, hi = TT;
            #pragma unroll
            for (int it = 0; it < 10; ++it) {
                int mid = (lo + hi) >> 1;
                if (csum[mid] <= t) lo = mid + 1; else hi = mid;
            }
            s = lo;
        }
        srcs[tid] = s;
    }
    __syncthreads();

    // ---- gather: 6144 float4 over 256 threads, direct LDG->STG ----
    const float4* __restrict__ xb = (const float4*)xs + (size_t)b * TT * V4;
    float4* __restrict__ ob = (float4*)out + ((size_t)b * OUT_LEN + r0) * V4;

    #pragma unroll 8
    for (int i = 0; i < ITERS; ++i) {               // 24 iters
        const int f = tid + i * NT;
        const int rl = f / V4;                       // mul-shift (const div)
        const int c = f - rl * V4;
        const int s = srcs[rl];                      // LDS
        float4 v = make_float4(0.f, 0.f, 0.f, 0.f);
        if (s >= 0) v = xb[s * V4 + c];              // coalesced, dups hit L2
        ob[f] = v;                                   // fully coalesced STG.128
    }
}

extern "C" void kernel_launch(void* const* d_in, const int* in_sizes, int n_in,
                              void* d_out, int out_size) {
    const float* xs = (const float*)d_in[0];
    const int* ds = (const int*)d_in[1];
    const int* ilens = (const int*)d_in[2];
    float* out = (float*)d_out;

    dim3 grid(BLOCKS_PER_B, BB);    // (56, 16) = 896 blocks
    lr_fused<<<grid, NT>>>(xs, ds, ilens, out);
}